// round 5
// baseline (speedup 1.0000x reference)
#include <cuda_runtime.h>
#include <cstdint>

#define M_TOT   8192
#define DM      1024
#define N_HEADS 16
#define HD      64
#define SEQ     2048

// Scratch (device globals: no allocation allowed in kernel_launch)
__device__ float g_Q[M_TOT * DM];
__device__ float g_K[M_TOT * DM];
__device__ float g_V[M_TOT * DM];
__device__ float g_A[M_TOT * DM];

// ---------------------------------------------------------------------------
// tf32 helpers
// ---------------------------------------------------------------------------
__device__ __forceinline__ uint32_t tf32_rna(float x) {
    uint32_t r;
    asm("cvt.rna.tf32.f32 %0, %1;" : "=r"(r) : "f"(x));   // b32 destination!
    return r;
}

__device__ __forceinline__ void mma_tf32(float* d, const uint32_t* a, const uint32_t* b) {
    asm volatile(
        "mma.sync.aligned.m16n8k8.row.col.f32.tf32.tf32.f32 "
        "{%0,%1,%2,%3}, {%4,%5,%6,%7}, {%8,%9}, {%0,%1,%2,%3};"
        : "+f"(d[0]), "+f"(d[1]), "+f"(d[2]), "+f"(d[3])
        : "r"(a[0]), "r"(a[1]), "r"(a[2]), "r"(a[3]), "r"(b[0]), "r"(b[1]));
}

// ---------------------------------------------------------------------------
// GEMM: C = A @ W^T + bias via 3xTF32 tensor-core passes (fp32-grade accuracy).
// A:[M][1024] row-major, W:[N=1024][1024] row-major (so W^T is col-major = mma "col").
// Block tile 128x64, K-stage 16, 256 threads = 8 warps (4 wm x 2 wn),
// warp tile 32x32 = 2x4 m16n8k8 fragments.
// Smem holds hi/lo tf32 planes in FRAGMENT ORDER:
//   A chunk (ks,mt): 32 lanes x 4 regs  -> LDS.128 per fragment, conflict-free
//   B chunk (ks,nt): 32 lanes x 2 regs  -> LDS.64  per fragment, conflict-free
// blockIdx.z selects among up to 3 (W,bias,C) triples (fused QKV launch).
// ---------------------------------------------------------------------------
#define GBM 128
#define GBN 64
#define GBK 16
// per-stage float counts
#define SA_SZ  2048   // 2 ks * 8 mtiles * 128
#define SB_SZ  1024   // 2 ks * 8 ntiles * 64
#define STAGE_FLOATS (2*SA_SZ + 2*SB_SZ)   // Ahi,Alo,Bhi,Blo = 6144 floats = 24KB

__global__ __launch_bounds__(256) void gemm_tf32_kernel(
    const float* __restrict__ Aglob,
    const float* __restrict__ W0, const float* __restrict__ W1, const float* __restrict__ W2,
    const float* __restrict__ b0, const float* __restrict__ b1, const float* __restrict__ b2,
    float* __restrict__ C0, float* __restrict__ C1, float* __restrict__ C2)
{
    extern __shared__ float smem[];   // 2 stages * 24KB = 48KB

    const int z = blockIdx.z;
    const float* W    = (z == 0) ? W0 : (z == 1) ? W1 : W2;
    const float* bias = (z == 0) ? b0 : (z == 1) ? b1 : b2;
    float*       C    = (z == 0) ? C0 : (z == 1) ? C1 : C2;

    const int t    = threadIdx.x;
    const int lane = t & 31;
    const int warp = t >> 5;
    const int wm   = warp >> 1;   // 0..3
    const int wn   = warp & 1;    // 0..1
    const int bm   = blockIdx.x * GBM;
    const int bn   = blockIdx.y * GBN;

    // global-load coordinates (per stage)
    const int a_m0 = t >> 2;              // rows t/4 and t/4+64
    const int a_kf = (t & 3) << 2;
    const int b_n  = t >> 2;
    const int b_kf = (t & 3) << 2;

    float acc[2][4][4];
#pragma unroll
    for (int i = 0; i < 2; i++)
#pragma unroll
        for (int j = 0; j < 4; j++)
#pragma unroll
            for (int c = 0; c < 4; c++) acc[i][j][c] = 0.f;

    float4 va[2], vb;

    // ---- helpers as lambdas ----
    auto fetch = [&](int k0) {
        va[0] = *(const float4*)(Aglob + (size_t)(bm + a_m0) * DM + k0 + a_kf);
        va[1] = *(const float4*)(Aglob + (size_t)(bm + a_m0 + 64) * DM + k0 + a_kf);
        vb    = *(const float4*)(W + (size_t)(bn + b_n) * DM + k0 + b_kf);
    };

    auto store_stage = [&](int buf) {
        float* sAhi = smem + buf * STAGE_FLOATS;
        float* sAlo = sAhi + SA_SZ;
        float* sBhi = sAlo + SA_SZ;
        float* sBlo = sBhi + SB_SZ;
#pragma unroll
        for (int i = 0; i < 2; i++) {
            const int m = a_m0 + i * 64;
            const int g = m & 7, rb0 = (m >> 3) & 1, mt = m >> 4;
            float vv[4] = {va[i].x, va[i].y, va[i].z, va[i].w};
#pragma unroll
            for (int e = 0; e < 4; e++) {
                int k = a_kf + e;
                int ks = k >> 3, kc = k & 7, tig = kc & 3, rb1 = kc >> 2;
                int pos = ((ks * 8 + mt) * 32 + g * 4 + tig) * 4 + rb0 + rb1 * 2;
                float hi = __uint_as_float(tf32_rna(vv[e]));
                sAhi[pos] = hi;
                sAlo[pos] = __uint_as_float(tf32_rna(vv[e] - hi));
            }
        }
        {
            const int n = b_n;
            const int g = n & 7, nt = n >> 3;
            float vv[4] = {vb.x, vb.y, vb.z, vb.w};
#pragma unroll
            for (int e = 0; e < 4; e++) {
                int k = b_kf + e;
                int ks = k >> 3, kc = k & 7, tig = kc & 3, r = kc >> 2;
                int pos = ((ks * 8 + nt) * 32 + g * 4 + tig) * 2 + r;
                float hi = __uint_as_float(tf32_rna(vv[e]));
                sBhi[pos] = hi;
                sBlo[pos] = __uint_as_float(tf32_rna(vv[e] - hi));
            }
        }
    };

    auto compute_stage = [&](int buf) {
        const float* sAhi = smem + buf * STAGE_FLOATS;
        const float* sAlo = sAhi + SA_SZ;
        const float* sBhi = sAlo + SA_SZ;
        const float* sBlo = sBhi + SB_SZ;
#pragma unroll
        for (int ks = 0; ks < 2; ks++) {
            uint4 ah[2], al[2];
            uint2 bh[4], bl[4];
#pragma unroll
            for (int i = 0; i < 2; i++) {
                int off = ((ks * 8 + wm * 2 + i) * 32 + lane) * 4;
                ah[i] = *(const uint4*)(sAhi + off);
                al[i] = *(const uint4*)(sAlo + off);
            }
#pragma unroll
            for (int j = 0; j < 4; j++) {
                int off = ((ks * 8 + wn * 4 + j) * 32 + lane) * 2;
                bh[j] = *(const uint2*)(sBhi + off);
                bl[j] = *(const uint2*)(sBlo + off);
            }
            // pass 1: hi*hi
#pragma unroll
            for (int i = 0; i < 2; i++)
#pragma unroll
                for (int j = 0; j < 4; j++)
                    mma_tf32(acc[i][j], (const uint32_t*)&ah[i], (const uint32_t*)&bh[j]);
            // pass 2: hi*lo
#pragma unroll
            for (int i = 0; i < 2; i++)
#pragma unroll
                for (int j = 0; j < 4; j++)
                    mma_tf32(acc[i][j], (const uint32_t*)&ah[i], (const uint32_t*)&bl[j]);
            // pass 3: lo*hi
#pragma unroll
            for (int i = 0; i < 2; i++)
#pragma unroll
                for (int j = 0; j < 4; j++)
                    mma_tf32(acc[i][j], (const uint32_t*)&al[i], (const uint32_t*)&bh[j]);
        }
    };

    // ---- pipelined main loop over 64 K-stages ----
    fetch(0);
    store_stage(0);
    const int NSTAGE = DM / GBK;   // 64
    for (int s = 0; s < NSTAGE; s++) {
        if (s + 1 < NSTAGE) fetch((s + 1) * GBK);
        __syncthreads();           // stage s smem visible to all
        compute_stage(s & 1);
        if (s + 1 < NSTAGE) store_stage((s + 1) & 1);
    }

    // ---- epilogue: bias + store ----
    const int g   = lane >> 2;
    const int tig = lane & 3;
#pragma unroll
    for (int i = 0; i < 2; i++) {
#pragma unroll
        for (int j = 0; j < 4; j++) {
            int row0 = bm + wm * 32 + i * 16 + g;
            int col  = bn + wn * 32 + j * 8 + tig * 2;
            float bvx = bias[col], bvy = bias[col + 1];
            float2 o0 = {acc[i][j][0] + bvx, acc[i][j][1] + bvy};
            float2 o1 = {acc[i][j][2] + bvx, acc[i][j][3] + bvy};
            *(float2*)(C + (size_t)row0 * DM + col)       = o0;
            *(float2*)(C + (size_t)(row0 + 8) * DM + col) = o1;
        }
    }
}

// ---------------------------------------------------------------------------
// Flash attention (causal), fp32. One block = 64 query rows of one (b,h).
// 128 threads as a 16(ty) x 8(tx) grid; each thread owns a 4x8 S / O tile.
// (unchanged from the passing R2 kernel)
// ---------------------------------------------------------------------------
__global__ __launch_bounds__(128) void attn_kernel()
{
    extern __shared__ float smem[];
    float* Qs = smem;                       // 64*64
    float* Kt = smem + 64 * 64;             // 64*65 (transposed K; later P[m][n])
    float* Vs = smem + 64 * 64 + 64 * 65;   // 64*64

    const int t  = threadIdx.x;
    const int tx = t & 7;
    const int ty = t >> 3;      // 0..15
    const int qt = blockIdx.x;  // query tile 0..31
    const int bh = blockIdx.y;  // 0..63
    const int b  = bh >> 4;
    const int h  = bh & 15;

    const size_t base = (size_t)b * SEQ * DM + (size_t)h * HD;

#pragma unroll
    for (int i = 0; i < 8; i++) {
        int idx = t + i * 128;
        int row = idx >> 4;
        int c   = (idx & 15) << 2;
        float4 v = *(const float4*)(g_Q + base + (size_t)(qt * 64 + row) * DM + c);
        v.x *= 0.125f; v.y *= 0.125f; v.z *= 0.125f; v.w *= 0.125f;
        *(float4*)&Qs[row * 64 + c] = v;
    }

    float O[4][8];
    float rmax[4], rsum[4];
#pragma unroll
    for (int i = 0; i < 4; i++) {
        rmax[i] = -1e30f;
        rsum[i] = 0.f;
#pragma unroll
        for (int c = 0; c < 8; c++) O[i][c] = 0.f;
    }

    for (int j = 0; j <= qt; j++) {
        __syncthreads();
#pragma unroll
        for (int i = 0; i < 8; i++) {
            int idx = t + i * 128;
            int row = idx >> 4;
            int c   = (idx & 15) << 2;
            float4 kv = *(const float4*)(g_K + base + (size_t)(j * 64 + row) * DM + c);
            Kt[(c + 0) * 65 + row] = kv.x;
            Kt[(c + 1) * 65 + row] = kv.y;
            Kt[(c + 2) * 65 + row] = kv.z;
            Kt[(c + 3) * 65 + row] = kv.w;
            float4 vv = *(const float4*)(g_V + base + (size_t)(j * 64 + row) * DM + c);
            *(float4*)&Vs[row * 64 + c] = vv;
        }
        __syncthreads();

        float S[4][8];
#pragma unroll
        for (int i = 0; i < 4; i++)
#pragma unroll
            for (int jj = 0; jj < 8; jj++) S[i][jj] = 0.f;

#pragma unroll 4
        for (int d = 0; d < 64; d++) {
            float qv[4], kv[8];
#pragma unroll
            for (int i = 0; i < 4; i++)  qv[i]  = Qs[(ty * 4 + i) * 64 + d];
#pragma unroll
            for (int jj = 0; jj < 8; jj++) kv[jj] = Kt[d * 65 + tx * 8 + jj];
#pragma unroll
            for (int i = 0; i < 4; i++)
#pragma unroll
                for (int jj = 0; jj < 8; jj++)
                    S[i][jj] += qv[i] * kv[jj];
        }

        if (j == qt) {
#pragma unroll
            for (int i = 0; i < 4; i++)
#pragma unroll
                for (int jj = 0; jj < 8; jj++)
                    if (tx * 8 + jj > ty * 4 + i) S[i][jj] = -1e30f;
        }

#pragma unroll
        for (int i = 0; i < 4; i++) {
            float mx = S[i][0];
#pragma unroll
            for (int jj = 1; jj < 8; jj++) mx = fmaxf(mx, S[i][jj]);
            mx = fmaxf(mx, __shfl_xor_sync(0xffffffffu, mx, 1));
            mx = fmaxf(mx, __shfl_xor_sync(0xffffffffu, mx, 2));
            mx = fmaxf(mx, __shfl_xor_sync(0xffffffffu, mx, 4));
            float mnew  = fmaxf(rmax[i], mx);
            float scale = __expf(rmax[i] - mnew);
            rmax[i] = mnew;
            float s = 0.f;
#pragma unroll
            for (int jj = 0; jj < 8; jj++) {
                S[i][jj] = __expf(S[i][jj] - mnew);
                s += S[i][jj];
            }
            s += __shfl_xor_sync(0xffffffffu, s, 1);
            s += __shfl_xor_sync(0xffffffffu, s, 2);
            s += __shfl_xor_sync(0xffffffffu, s, 4);
            rsum[i] = rsum[i] * scale + s;
#pragma unroll
            for (int c = 0; c < 8; c++) O[i][c] *= scale;
        }

        __syncthreads();
#pragma unroll
        for (int i = 0; i < 4; i++)
#pragma unroll
            for (int jj = 0; jj < 8; jj++)
                Kt[(ty * 4 + i) * 65 + tx * 8 + jj] = S[i][jj];
        __syncthreads();

#pragma unroll 4
        for (int n = 0; n < 64; n++) {
            float pv[4], vv[8];
#pragma unroll
            for (int i = 0; i < 4; i++) pv[i] = Kt[(ty * 4 + i) * 65 + n];
#pragma unroll
            for (int c = 0; c < 8; c++) vv[c] = Vs[n * 64 + tx * 8 + c];
#pragma unroll
            for (int i = 0; i < 4; i++)
#pragma unroll
                for (int c = 0; c < 8; c++)
                    O[i][c] += pv[i] * vv[c];
        }
    }

#pragma unroll
    for (int i = 0; i < 4; i++) {
        float inv = 1.0f / rsum[i];
        int row = qt * 64 + ty * 4 + i;
        float4 o0, o1;
        o0.x = O[i][0] * inv; o0.y = O[i][1] * inv;
        o0.z = O[i][2] * inv; o0.w = O[i][3] * inv;
        o1.x = O[i][4] * inv; o1.y = O[i][5] * inv;
        o1.z = O[i][6] * inv; o1.w = O[i][7] * inv;
        *(float4*)(g_A + base + (size_t)row * DM + tx * 8)     = o0;
        *(float4*)(g_A + base + (size_t)row * DM + tx * 8 + 4) = o1;
    }
}

// ---------------------------------------------------------------------------
extern "C" void kernel_launch(void* const* d_in, const int* in_sizes, int n_in,
                              void* d_out, int out_size)
{
    // Size-driven input classification:
    //   8388608 elems -> x;  1048576 -> weights (Wq,Wk,Wv,Wo in order);
    //   1024 -> biases (bq,bk,bv,bo in order).
    const float* x = 0;
    const float* Ws[4] = {0, 0, 0, 0};
    const float* bs[4] = {0, 0, 0, 0};
    int nw = 0, nb = 0;
    for (int i = 0; i < n_in; i++) {
        if (in_sizes[i] == M_TOT * DM)      x = (const float*)d_in[i];
        else if (in_sizes[i] == DM * DM)    { if (nw < 4) Ws[nw++] = (const float*)d_in[i]; }
        else if (in_sizes[i] == DM)         { if (nb < 4) bs[nb++] = (const float*)d_in[i]; }
    }
    const float *Wq = Ws[0], *Wk = Ws[1], *Wv = Ws[2], *Wo = Ws[3];
    const float *bq = bs[0], *bk = bs[1], *bv = bs[2], *bo = bs[3];
    float* out = (float*)d_out;

    void *pQ, *pK, *pV, *pA;
    cudaGetSymbolAddress(&pQ, g_Q);
    cudaGetSymbolAddress(&pK, g_K);
    cudaGetSymbolAddress(&pV, g_V);
    cudaGetSymbolAddress(&pA, g_A);

    const int gemm_smem = 2 * STAGE_FLOATS * (int)sizeof(float);   // 49152 B
    cudaFuncSetAttribute(gemm_tf32_kernel, cudaFuncAttributeMaxDynamicSharedMemorySize, gemm_smem);

    // 1) Fused Q/K/V projections (tensor cores, 3xTF32)
    gemm_tf32_kernel<<<dim3(M_TOT / GBM, DM / GBN, 3), 256, gemm_smem>>>(
        x, Wq, Wk, Wv, bq, bk, bv, (float*)pQ, (float*)pK, (float*)pV);

    // 2) Causal flash attention (fp32 SIMT)
    const int attn_smem = (64 * 64 + 64 * 65 + 64 * 64) * (int)sizeof(float); // 49408 B
    cudaFuncSetAttribute(attn_kernel, cudaFuncAttributeMaxDynamicSharedMemorySize, attn_smem);
    attn_kernel<<<dim3(SEQ / 64, 4 * N_HEADS), 128, attn_smem>>>();

    // 3) Output projection -> d_out (tensor cores, 3xTF32)
    gemm_tf32_kernel<<<dim3(M_TOT / GBM, DM / GBN, 1), 256, gemm_smem>>>(
        (const float*)pA, Wo, Wo, Wo, bo, bo, bo, out, out, out);
}

// round 6
// speedup vs baseline: 1.2634x; 1.2634x over previous
#include <cuda_runtime.h>
#include <cstdint>

#define M_TOT   8192
#define DM      1024
#define N_HEADS 16
#define HD      64
#define SEQ     2048

// Scratch (device globals: no allocation allowed in kernel_launch)
__device__ float g_Q[M_TOT * DM];
__device__ float g_K[M_TOT * DM];
__device__ float g_V[M_TOT * DM];
__device__ float g_A[M_TOT * DM];

// ---------------------------------------------------------------------------
// tf32 / async-copy helpers
// ---------------------------------------------------------------------------
__device__ __forceinline__ uint32_t tf32_rna(float x) {
    uint32_t r;
    asm("cvt.rna.tf32.f32 %0, %1;" : "=r"(r) : "f"(x));
    return r;
}

__device__ __forceinline__ void mma_tf32(float* d, const uint32_t* a, const uint32_t* b) {
    asm volatile(
        "mma.sync.aligned.m16n8k8.row.col.f32.tf32.tf32.f32 "
        "{%0,%1,%2,%3}, {%4,%5,%6,%7}, {%8,%9}, {%0,%1,%2,%3};"
        : "+f"(d[0]), "+f"(d[1]), "+f"(d[2]), "+f"(d[3])
        : "r"(a[0]), "r"(a[1]), "r"(a[2]), "r"(a[3]), "r"(b[0]), "r"(b[1]));
}

__device__ __forceinline__ uint32_t smem_addr_u32(const void* p) {
    uint32_t a;
    asm("{ .reg .u64 t; cvta.to.shared.u64 t, %1; cvt.u32.u64 %0, t; }" : "=r"(a) : "l"(p));
    return a;
}

__device__ __forceinline__ void cp16(uint32_t dst, const void* src) {
    asm volatile("cp.async.cg.shared.global [%0], [%1], 16;" :: "r"(dst), "l"(src));
}

// ---------------------------------------------------------------------------
// GEMM: C = A @ W^T + bias via 3xTF32 (hi/lo split computed in REGISTERS).
// Smem holds RAW fp32 tiles in natural [row][k] layout, row stride 36 floats
// (pad 4) -> every consumer fragment LDS is conflict-free, producer side is
// pure cp.async (no STS at all). Block tile 128x64, BK=32, 2-stage pipeline,
// 256 threads = 8 warps (4 wm x 2 wn), warp tile 32x32 = 2x4 m16n8k8 frags.
// blockIdx.z selects among up to 3 (W,bias,C) triples (fused QKV launch).
// ---------------------------------------------------------------------------
#define GBM 128
#define GBN 64
#define GBK 32
#define SAS 36                                // padded row stride in floats
#define SA_FLOATS (128 * SAS)                 // 4608
#define SB_FLOATS (64 * SAS)                  // 2304
#define STAGE_FLOATS (SA_FLOATS + SB_FLOATS)  // 6912 floats = 27648 B / stage

__global__ __launch_bounds__(256) void gemm_tf32_kernel(
    const float* __restrict__ Aglob,
    const float* __restrict__ W0, const float* __restrict__ W1, const float* __restrict__ W2,
    const float* __restrict__ b0, const float* __restrict__ b1, const float* __restrict__ b2,
    float* __restrict__ C0, float* __restrict__ C1, float* __restrict__ C2)
{
    extern __shared__ float smem[];   // 2 stages * 27648 B = 55296 B

    const int z = blockIdx.z;
    const float* W    = (z == 0) ? W0 : (z == 1) ? W1 : W2;
    const float* bias = (z == 0) ? b0 : (z == 1) ? b1 : b2;
    float*       C    = (z == 0) ? C0 : (z == 1) ? C1 : C2;

    const int t    = threadIdx.x;
    const int lane = t & 31;
    const int warp = t >> 5;
    const int wm   = warp >> 1;   // 0..3
    const int wn   = warp & 1;    // 0..1
    const int bm   = blockIdx.x * GBM;
    const int bn   = blockIdx.y * GBN;
    const int g    = lane >> 2;   // fragment row/col group
    const int tig  = lane & 3;    // fragment k (low)

    const uint32_t sbase = smem_addr_u32(smem);

    float acc[2][4][4];
#pragma unroll
    for (int i = 0; i < 2; i++)
#pragma unroll
        for (int j = 0; j < 4; j++)
#pragma unroll
            for (int c = 0; c < 4; c++) acc[i][j][c] = 0.f;

    // ---- async copy of one K-stage (raw fp32, vectorized, no STS) ----
    auto copy_stage = [&](int buf, int k0) {
        uint32_t sA = sbase + (uint32_t)(buf * STAGE_FLOATS) * 4u;
        uint32_t sB = sA + (uint32_t)SA_FLOATS * 4u;
#pragma unroll
        for (int i = 0; i < 4; i++) {           // A: 128 rows x 8 float4 cols
            int idx = t + i * 256;
            int row = idx >> 3;
            int c4  = (idx & 7) << 2;
            cp16(sA + (uint32_t)(row * SAS + c4) * 4u,
                 Aglob + (size_t)(bm + row) * DM + k0 + c4);
        }
#pragma unroll
        for (int i = 0; i < 2; i++) {           // B: 64 rows x 8 float4 cols
            int idx = t + i * 256;
            int row = idx >> 3;
            int c4  = (idx & 7) << 2;
            cp16(sB + (uint32_t)(row * SAS + c4) * 4u,
                 W + (size_t)(bn + row) * DM + k0 + c4);
        }
        asm volatile("cp.async.commit_group;" ::: "memory");
    };

    // ---- compute one K-stage: raw LDS -> reg hi/lo split -> 3 mma passes ----
    auto compute_stage = [&](int buf) {
        const float* sA = smem + buf * STAGE_FLOATS;
        const float* sB = sA + SA_FLOATS;
#pragma unroll
        for (int ks = 0; ks < 4; ks++) {
            const int kc = ks * 8 + tig;
            uint32_t ah[2][4], al[2][4];
#pragma unroll
            for (int i = 0; i < 2; i++) {
                int base = (wm * 32 + i * 16 + g) * SAS + kc;
                float r0 = sA[base];
                float r1 = sA[base + 8 * SAS];
                float r2 = sA[base + 4];
                float r3 = sA[base + 8 * SAS + 4];
                ah[i][0] = tf32_rna(r0); al[i][0] = tf32_rna(r0 - __uint_as_float(ah[i][0]));
                ah[i][1] = tf32_rna(r1); al[i][1] = tf32_rna(r1 - __uint_as_float(ah[i][1]));
                ah[i][2] = tf32_rna(r2); al[i][2] = tf32_rna(r2 - __uint_as_float(ah[i][2]));
                ah[i][3] = tf32_rna(r3); al[i][3] = tf32_rna(r3 - __uint_as_float(ah[i][3]));
            }
            uint32_t bh[4][2], bl[4][2];
#pragma unroll
            for (int j = 0; j < 4; j++) {
                int base = (wn * 32 + j * 8 + g) * SAS + kc;
                float r0 = sB[base];
                float r1 = sB[base + 4];
                bh[j][0] = tf32_rna(r0); bl[j][0] = tf32_rna(r0 - __uint_as_float(bh[j][0]));
                bh[j][1] = tf32_rna(r1); bl[j][1] = tf32_rna(r1 - __uint_as_float(bh[j][1]));
            }
            // pass 1: hi*hi
#pragma unroll
            for (int i = 0; i < 2; i++)
#pragma unroll
                for (int j = 0; j < 4; j++)
                    mma_tf32(acc[i][j], ah[i], bh[j]);
            // pass 2: hi*lo
#pragma unroll
            for (int i = 0; i < 2; i++)
#pragma unroll
                for (int j = 0; j < 4; j++)
                    mma_tf32(acc[i][j], ah[i], bl[j]);
            // pass 3: lo*hi
#pragma unroll
            for (int i = 0; i < 2; i++)
#pragma unroll
                for (int j = 0; j < 4; j++)
                    mma_tf32(acc[i][j], al[i], bh[j]);
        }
    };

    // ---- 2-stage cp.async pipeline over 32 K-stages ----
    copy_stage(0, 0);
    const int NS = DM / GBK;   // 32
    for (int s = 0; s < NS; s++) {
        asm volatile("cp.async.wait_group 0;" ::: "memory");
        __syncthreads();       // stage s visible to all; all done with buf (s+1)&1
        if (s + 1 < NS) copy_stage((s + 1) & 1, (s + 1) * GBK);
        compute_stage(s & 1);
    }

    // ---- epilogue: bias + store ----
#pragma unroll
    for (int i = 0; i < 2; i++) {
#pragma unroll
        for (int j = 0; j < 4; j++) {
            int row0 = bm + wm * 32 + i * 16 + g;
            int col  = bn + wn * 32 + j * 8 + tig * 2;
            float bvx = bias[col], bvy = bias[col + 1];
            float2 o0 = {acc[i][j][0] + bvx, acc[i][j][1] + bvy};
            float2 o1 = {acc[i][j][2] + bvx, acc[i][j][3] + bvy};
            *(float2*)(C + (size_t)row0 * DM + col)       = o0;
            *(float2*)(C + (size_t)(row0 + 8) * DM + col) = o1;
        }
    }
}

// ---------------------------------------------------------------------------
// Flash attention (causal), fp32. One block = 64 query rows of one (b,h).
// 128 threads as a 16(ty) x 8(tx) grid; each thread owns a 4x8 S / O tile.
// (unchanged from the passing R2/R5 kernel)
// ---------------------------------------------------------------------------
__global__ __launch_bounds__(128) void attn_kernel()
{
    extern __shared__ float smem[];
    float* Qs = smem;                       // 64*64
    float* Kt = smem + 64 * 64;             // 64*65 (transposed K; later P[m][n])
    float* Vs = smem + 64 * 64 + 64 * 65;   // 64*64

    const int t  = threadIdx.x;
    const int tx = t & 7;
    const int ty = t >> 3;      // 0..15
    const int qt = blockIdx.x;  // query tile 0..31
    const int bh = blockIdx.y;  // 0..63
    const int b  = bh >> 4;
    const int h  = bh & 15;

    const size_t base = (size_t)b * SEQ * DM + (size_t)h * HD;

#pragma unroll
    for (int i = 0; i < 8; i++) {
        int idx = t + i * 128;
        int row = idx >> 4;
        int c   = (idx & 15) << 2;
        float4 v = *(const float4*)(g_Q + base + (size_t)(qt * 64 + row) * DM + c);
        v.x *= 0.125f; v.y *= 0.125f; v.z *= 0.125f; v.w *= 0.125f;
        *(float4*)&Qs[row * 64 + c] = v;
    }

    float O[4][8];
    float rmax[4], rsum[4];
#pragma unroll
    for (int i = 0; i < 4; i++) {
        rmax[i] = -1e30f;
        rsum[i] = 0.f;
#pragma unroll
        for (int c = 0; c < 8; c++) O[i][c] = 0.f;
    }

    for (int j = 0; j <= qt; j++) {
        __syncthreads();
#pragma unroll
        for (int i = 0; i < 8; i++) {
            int idx = t + i * 128;
            int row = idx >> 4;
            int c   = (idx & 15) << 2;
            float4 kv = *(const float4*)(g_K + base + (size_t)(j * 64 + row) * DM + c);
            Kt[(c + 0) * 65 + row] = kv.x;
            Kt[(c + 1) * 65 + row] = kv.y;
            Kt[(c + 2) * 65 + row] = kv.z;
            Kt[(c + 3) * 65 + row] = kv.w;
            float4 vv = *(const float4*)(g_V + base + (size_t)(j * 64 + row) * DM + c);
            *(float4*)&Vs[row * 64 + c] = vv;
        }
        __syncthreads();

        float S[4][8];
#pragma unroll
        for (int i = 0; i < 4; i++)
#pragma unroll
            for (int jj = 0; jj < 8; jj++) S[i][jj] = 0.f;

#pragma unroll 4
        for (int d = 0; d < 64; d++) {
            float qv[4], kv[8];
#pragma unroll
            for (int i = 0; i < 4; i++)  qv[i]  = Qs[(ty * 4 + i) * 64 + d];
#pragma unroll
            for (int jj = 0; jj < 8; jj++) kv[jj] = Kt[d * 65 + tx * 8 + jj];
#pragma unroll
            for (int i = 0; i < 4; i++)
#pragma unroll
                for (int jj = 0; jj < 8; jj++)
                    S[i][jj] += qv[i] * kv[jj];
        }

        if (j == qt) {
#pragma unroll
            for (int i = 0; i < 4; i++)
#pragma unroll
                for (int jj = 0; jj < 8; jj++)
                    if (tx * 8 + jj > ty * 4 + i) S[i][jj] = -1e30f;
        }

#pragma unroll
        for (int i = 0; i < 4; i++) {
            float mx = S[i][0];
#pragma unroll
            for (int jj = 1; jj < 8; jj++) mx = fmaxf(mx, S[i][jj]);
            mx = fmaxf(mx, __shfl_xor_sync(0xffffffffu, mx, 1));
            mx = fmaxf(mx, __shfl_xor_sync(0xffffffffu, mx, 2));
            mx = fmaxf(mx, __shfl_xor_sync(0xffffffffu, mx, 4));
            float mnew  = fmaxf(rmax[i], mx);
            float scale = __expf(rmax[i] - mnew);
            rmax[i] = mnew;
            float s = 0.f;
#pragma unroll
            for (int jj = 0; jj < 8; jj++) {
                S[i][jj] = __expf(S[i][jj] - mnew);
                s += S[i][jj];
            }
            s += __shfl_xor_sync(0xffffffffu, s, 1);
            s += __shfl_xor_sync(0xffffffffu, s, 2);
            s += __shfl_xor_sync(0xffffffffu, s, 4);
            rsum[i] = rsum[i] * scale + s;
#pragma unroll
            for (int c = 0; c < 8; c++) O[i][c] *= scale;
        }

        __syncthreads();
#pragma unroll
        for (int i = 0; i < 4; i++)
#pragma unroll
            for (int jj = 0; jj < 8; jj++)
                Kt[(ty * 4 + i) * 65 + tx * 8 + jj] = S[i][jj];
        __syncthreads();

#pragma unroll 4
        for (int n = 0; n < 64; n++) {
            float pv[4], vv[8];
#pragma unroll
            for (int i = 0; i < 4; i++) pv[i] = Kt[(ty * 4 + i) * 65 + n];
#pragma unroll
            for (int c = 0; c < 8; c++) vv[c] = Vs[n * 64 + tx * 8 + c];
#pragma unroll
            for (int i = 0; i < 4; i++)
#pragma unroll
                for (int c = 0; c < 8; c++)
                    O[i][c] += pv[i] * vv[c];
        }
    }

#pragma unroll
    for (int i = 0; i < 4; i++) {
        float inv = 1.0f / rsum[i];
        int row = qt * 64 + ty * 4 + i;
        float4 o0, o1;
        o0.x = O[i][0] * inv; o0.y = O[i][1] * inv;
        o0.z = O[i][2] * inv; o0.w = O[i][3] * inv;
        o1.x = O[i][4] * inv; o1.y = O[i][5] * inv;
        o1.z = O[i][6] * inv; o1.w = O[i][7] * inv;
        *(float4*)(g_A + base + (size_t)row * DM + tx * 8)     = o0;
        *(float4*)(g_A + base + (size_t)row * DM + tx * 8 + 4) = o1;
    }
}

// ---------------------------------------------------------------------------
extern "C" void kernel_launch(void* const* d_in, const int* in_sizes, int n_in,
                              void* d_out, int out_size)
{
    // Size-driven input classification:
    //   8388608 elems -> x;  1048576 -> weights (Wq,Wk,Wv,Wo in order);
    //   1024 -> biases (bq,bk,bv,bo in order).
    const float* x = 0;
    const float* Ws[4] = {0, 0, 0, 0};
    const float* bs[4] = {0, 0, 0, 0};
    int nw = 0, nb = 0;
    for (int i = 0; i < n_in; i++) {
        if (in_sizes[i] == M_TOT * DM)      x = (const float*)d_in[i];
        else if (in_sizes[i] == DM * DM)    { if (nw < 4) Ws[nw++] = (const float*)d_in[i]; }
        else if (in_sizes[i] == DM)         { if (nb < 4) bs[nb++] = (const float*)d_in[i]; }
    }
    const float *Wq = Ws[0], *Wk = Ws[1], *Wv = Ws[2], *Wo = Ws[3];
    const float *bq = bs[0], *bk = bs[1], *bv = bs[2], *bo = bs[3];
    float* out = (float*)d_out;

    void *pQ, *pK, *pV, *pA;
    cudaGetSymbolAddress(&pQ, g_Q);
    cudaGetSymbolAddress(&pK, g_K);
    cudaGetSymbolAddress(&pV, g_V);
    cudaGetSymbolAddress(&pA, g_A);

    const int gemm_smem = 2 * STAGE_FLOATS * (int)sizeof(float);   // 55296 B
    cudaFuncSetAttribute(gemm_tf32_kernel, cudaFuncAttributeMaxDynamicSharedMemorySize, gemm_smem);

    // 1) Fused Q/K/V projections (tensor cores, 3xTF32, cp.async pipeline)
    gemm_tf32_kernel<<<dim3(M_TOT / GBM, DM / GBN, 3), 256, gemm_smem>>>(
        x, Wq, Wk, Wv, bq, bk, bv, (float*)pQ, (float*)pK, (float*)pV);

    // 2) Causal flash attention (fp32 SIMT)
    const int attn_smem = (64 * 64 + 64 * 65 + 64 * 64) * (int)sizeof(float); // 49408 B
    cudaFuncSetAttribute(attn_kernel, cudaFuncAttributeMaxDynamicSharedMemorySize, attn_smem);
    attn_kernel<<<dim3(SEQ / 64, 4 * N_HEADS), 128, attn_smem>>>();

    // 3) Output projection -> d_out (tensor cores, 3xTF32)
    gemm_tf32_kernel<<<dim3(M_TOT / GBM, DM / GBN, 1), 256, gemm_smem>>>(
        (const float*)pA, Wo, Wo, Wo, bo, bo, bo, out, out, out);
}

// round 7
// speedup vs baseline: 1.4765x; 1.1687x over previous
#include <cuda_runtime.h>
#include <cstdint>

#define M_TOT   8192
#define DM      1024
#define N_HEADS 16
#define HD      64
#define SEQ     2048

// Scratch (device globals: no allocation allowed in kernel_launch)
__device__ float g_Q[M_TOT * DM];
__device__ float g_K[M_TOT * DM];
__device__ float g_V[M_TOT * DM];
__device__ float g_A[M_TOT * DM];

// ---------------------------------------------------------------------------
// tf32 / async-copy helpers
// ---------------------------------------------------------------------------
__device__ __forceinline__ uint32_t tf32_rna(float x) {
    uint32_t r;
    asm("cvt.rna.tf32.f32 %0, %1;" : "=r"(r) : "f"(x));
    return r;
}

__device__ __forceinline__ void mma_tf32(float* d, const uint32_t* a, const uint32_t* b) {
    asm volatile(
        "mma.sync.aligned.m16n8k8.row.col.f32.tf32.tf32.f32 "
        "{%0,%1,%2,%3}, {%4,%5,%6,%7}, {%8,%9}, {%0,%1,%2,%3};"
        : "+f"(d[0]), "+f"(d[1]), "+f"(d[2]), "+f"(d[3])
        : "r"(a[0]), "r"(a[1]), "r"(a[2]), "r"(a[3]), "r"(b[0]), "r"(b[1]));
}

__device__ __forceinline__ uint32_t smem_addr_u32(const void* p) {
    uint32_t a;
    asm("{ .reg .u64 t; cvta.to.shared.u64 t, %1; cvt.u32.u64 %0, t; }" : "=r"(a) : "l"(p));
    return a;
}

__device__ __forceinline__ void cp16(uint32_t dst, const void* src) {
    asm volatile("cp.async.cg.shared.global [%0], [%1], 16;" :: "r"(dst), "l"(src));
}

// ---------------------------------------------------------------------------
// GEMM: C = A @ W^T + bias via 3xTF32 (hi/lo split computed in REGISTERS).
// (byte-identical to the R6 winning version)
// ---------------------------------------------------------------------------
#define GBM 128
#define GBN 64
#define GBK 32
#define SAS 36
#define SA_FLOATS (128 * SAS)
#define SB_FLOATS (64 * SAS)
#define STAGE_FLOATS (SA_FLOATS + SB_FLOATS)

__global__ __launch_bounds__(256) void gemm_tf32_kernel(
    const float* __restrict__ Aglob,
    const float* __restrict__ W0, const float* __restrict__ W1, const float* __restrict__ W2,
    const float* __restrict__ b0, const float* __restrict__ b1, const float* __restrict__ b2,
    float* __restrict__ C0, float* __restrict__ C1, float* __restrict__ C2)
{
    extern __shared__ float smem[];

    const int z = blockIdx.z;
    const float* W    = (z == 0) ? W0 : (z == 1) ? W1 : W2;
    const float* bias = (z == 0) ? b0 : (z == 1) ? b1 : b2;
    float*       C    = (z == 0) ? C0 : (z == 1) ? C1 : C2;

    const int t    = threadIdx.x;
    const int lane = t & 31;
    const int warp = t >> 5;
    const int wm   = warp >> 1;
    const int wn   = warp & 1;
    const int bm   = blockIdx.x * GBM;
    const int bn   = blockIdx.y * GBN;
    const int g    = lane >> 2;
    const int tig  = lane & 3;

    const uint32_t sbase = smem_addr_u32(smem);

    float acc[2][4][4];
#pragma unroll
    for (int i = 0; i < 2; i++)
#pragma unroll
        for (int j = 0; j < 4; j++)
#pragma unroll
            for (int c = 0; c < 4; c++) acc[i][j][c] = 0.f;

    auto copy_stage = [&](int buf, int k0) {
        uint32_t sA = sbase + (uint32_t)(buf * STAGE_FLOATS) * 4u;
        uint32_t sB = sA + (uint32_t)SA_FLOATS * 4u;
#pragma unroll
        for (int i = 0; i < 4; i++) {
            int idx = t + i * 256;
            int row = idx >> 3;
            int c4  = (idx & 7) << 2;
            cp16(sA + (uint32_t)(row * SAS + c4) * 4u,
                 Aglob + (size_t)(bm + row) * DM + k0 + c4);
        }
#pragma unroll
        for (int i = 0; i < 2; i++) {
            int idx = t + i * 256;
            int row = idx >> 3;
            int c4  = (idx & 7) << 2;
            cp16(sB + (uint32_t)(row * SAS + c4) * 4u,
                 W + (size_t)(bn + row) * DM + k0 + c4);
        }
        asm volatile("cp.async.commit_group;" ::: "memory");
    };

    auto compute_stage = [&](int buf) {
        const float* sA = smem + buf * STAGE_FLOATS;
        const float* sB = sA + SA_FLOATS;
#pragma unroll
        for (int ks = 0; ks < 4; ks++) {
            const int kc = ks * 8 + tig;
            uint32_t ah[2][4], al[2][4];
#pragma unroll
            for (int i = 0; i < 2; i++) {
                int base = (wm * 32 + i * 16 + g) * SAS + kc;
                float r0 = sA[base];
                float r1 = sA[base + 8 * SAS];
                float r2 = sA[base + 4];
                float r3 = sA[base + 8 * SAS + 4];
                ah[i][0] = tf32_rna(r0); al[i][0] = tf32_rna(r0 - __uint_as_float(ah[i][0]));
                ah[i][1] = tf32_rna(r1); al[i][1] = tf32_rna(r1 - __uint_as_float(ah[i][1]));
                ah[i][2] = tf32_rna(r2); al[i][2] = tf32_rna(r2 - __uint_as_float(ah[i][2]));
                ah[i][3] = tf32_rna(r3); al[i][3] = tf32_rna(r3 - __uint_as_float(ah[i][3]));
            }
            uint32_t bh[4][2], bl[4][2];
#pragma unroll
            for (int j = 0; j < 4; j++) {
                int base = (wn * 32 + j * 8 + g) * SAS + kc;
                float r0 = sB[base];
                float r1 = sB[base + 4];
                bh[j][0] = tf32_rna(r0); bl[j][0] = tf32_rna(r0 - __uint_as_float(bh[j][0]));
                bh[j][1] = tf32_rna(r1); bl[j][1] = tf32_rna(r1 - __uint_as_float(bh[j][1]));
            }
#pragma unroll
            for (int i = 0; i < 2; i++)
#pragma unroll
                for (int j = 0; j < 4; j++)
                    mma_tf32(acc[i][j], ah[i], bh[j]);
#pragma unroll
            for (int i = 0; i < 2; i++)
#pragma unroll
                for (int j = 0; j < 4; j++)
                    mma_tf32(acc[i][j], ah[i], bl[j]);
#pragma unroll
            for (int i = 0; i < 2; i++)
#pragma unroll
                for (int j = 0; j < 4; j++)
                    mma_tf32(acc[i][j], al[i], bh[j]);
        }
    };

    copy_stage(0, 0);
    const int NS = DM / GBK;
    for (int s = 0; s < NS; s++) {
        asm volatile("cp.async.wait_group 0;" ::: "memory");
        __syncthreads();
        if (s + 1 < NS) copy_stage((s + 1) & 1, (s + 1) * GBK);
        compute_stage(s & 1);
    }

#pragma unroll
    for (int i = 0; i < 2; i++) {
#pragma unroll
        for (int j = 0; j < 4; j++) {
            int row0 = bm + wm * 32 + i * 16 + g;
            int col  = bn + wn * 32 + j * 8 + tig * 2;
            float bvx = bias[col], bvy = bias[col + 1];
            float2 o0 = {acc[i][j][0] + bvx, acc[i][j][1] + bvy};
            float2 o1 = {acc[i][j][2] + bvx, acc[i][j][3] + bvy};
            *(float2*)(C + (size_t)row0 * DM + col)       = o0;
            *(float2*)(C + (size_t)(row0 + 8) * DM + col) = o1;
        }
    }
}

// ---------------------------------------------------------------------------
// Flash attention v2 (causal), fp32 SIMT.
// One block = 128 query rows of one (b,h); 64-key tiles.
// 128 threads as 16(ty) x 8(tx); each thread owns an 8x8 S / O register tile
//   rows ty*8..ty*8+7 (128 rows), cols tx*8..tx*8+7 (64 cols).
// Q is transposed into smem ONCE per block (Qt[d][row], broadcast-friendly),
// K transposed per tile (Kt[d][key]), V natural, P in its own buffer.
// smem: Qt[64][130] | Kt[64][65] | Vs[64][64] | Ps[128][65]  = 99584 B
// ---------------------------------------------------------------------------
__global__ __launch_bounds__(128) void attn_kernel()
{
    extern __shared__ float smem[];
    float* Qt = smem;                     // 64*130
    float* Kt = Qt + 64 * 130;            // 64*65
    float* Vs = Kt + 64 * 65;             // 64*64
    float* Ps = Vs + 64 * 64;             // 128*65

    const int t  = threadIdx.x;
    const int tx = t & 7;
    const int ty = t >> 3;                    // 0..15
    const int qt = 15 - (int)blockIdx.x;      // big tiles scheduled first
    const int bh = blockIdx.y;                // 0..63
    const int b  = bh >> 4;
    const int h  = bh & 15;

    const size_t base = (size_t)b * SEQ * DM + (size_t)h * HD;

    // Load Q tile (128 rows x 64 dims), prescale by 1/sqrt(64), transpose.
#pragma unroll
    for (int i = 0; i < 16; i++) {
        int idx = t + i * 128;
        int row = idx >> 4;            // 0..127
        int c   = (idx & 15) << 2;     // 0..60
        float4 v = *(const float4*)(g_Q + base + (size_t)(qt * 128 + row) * DM + c);
        Qt[(c + 0) * 130 + row] = v.x * 0.125f;
        Qt[(c + 1) * 130 + row] = v.y * 0.125f;
        Qt[(c + 2) * 130 + row] = v.z * 0.125f;
        Qt[(c + 3) * 130 + row] = v.w * 0.125f;
    }

    float O[8][8];
    float rmax[8], rsum[8];
#pragma unroll
    for (int i = 0; i < 8; i++) {
        rmax[i] = -1e30f;
        rsum[i] = 0.f;
#pragma unroll
        for (int c = 0; c < 8; c++) O[i][c] = 0.f;
    }

    const int nj = 2 * qt + 2;     // key tiles 0 .. 2qt+1
    for (int j = 0; j < nj; j++) {
        __syncthreads();   // prev PV done with Vs; also makes Qt visible (j=0)
#pragma unroll
        for (int i = 0; i < 8; i++) {
            int idx = t + i * 128;
            int row = idx >> 4;        // key 0..63
            int c   = (idx & 15) << 2;
            float4 kv4 = *(const float4*)(g_K + base + (size_t)(j * 64 + row) * DM + c);
            Kt[(c + 0) * 65 + row] = kv4.x;
            Kt[(c + 1) * 65 + row] = kv4.y;
            Kt[(c + 2) * 65 + row] = kv4.z;
            Kt[(c + 3) * 65 + row] = kv4.w;
            float4 vv4 = *(const float4*)(g_V + base + (size_t)(j * 64 + row) * DM + c);
            *(float4*)&Vs[row * 64 + c] = vv4;
        }
        __syncthreads();

        // S = (Q/8) @ K^T   (8x8 per thread)
        float S[8][8];
#pragma unroll
        for (int i = 0; i < 8; i++)
#pragma unroll
            for (int jj = 0; jj < 8; jj++) S[i][jj] = 0.f;

#pragma unroll 2
        for (int d = 0; d < 64; d++) {
            float qv[8], kv[8];
#pragma unroll
            for (int i = 0; i < 8; i++)  qv[i]  = Qt[d * 130 + ty * 8 + i];
#pragma unroll
            for (int jj = 0; jj < 8; jj++) kv[jj] = Kt[d * 65 + tx * 8 + jj];
#pragma unroll
            for (int i = 0; i < 8; i++)
#pragma unroll
                for (int jj = 0; jj < 8; jj++)
                    S[i][jj] += qv[i] * kv[jj];
        }

        if (j >= 2 * qt) {   // (partially) diagonal tiles: causal mask
#pragma unroll
            for (int i = 0; i < 8; i++) {
                int qrow = qt * 128 + ty * 8 + i;
#pragma unroll
                for (int jj = 0; jj < 8; jj++)
                    if (j * 64 + tx * 8 + jj > qrow) S[i][jj] = -1e30f;
            }
        }

        // Online softmax: 8 local cols + butterfly across the row's octet.
#pragma unroll
        for (int i = 0; i < 8; i++) {
            float mx = S[i][0];
#pragma unroll
            for (int jj = 1; jj < 8; jj++) mx = fmaxf(mx, S[i][jj]);
            mx = fmaxf(mx, __shfl_xor_sync(0xffffffffu, mx, 1));
            mx = fmaxf(mx, __shfl_xor_sync(0xffffffffu, mx, 2));
            mx = fmaxf(mx, __shfl_xor_sync(0xffffffffu, mx, 4));
            float mnew  = fmaxf(rmax[i], mx);
            float scale = __expf(rmax[i] - mnew);
            rmax[i] = mnew;
            float s = 0.f;
#pragma unroll
            for (int jj = 0; jj < 8; jj++) {
                S[i][jj] = __expf(S[i][jj] - mnew);
                s += S[i][jj];
            }
            s += __shfl_xor_sync(0xffffffffu, s, 1);
            s += __shfl_xor_sync(0xffffffffu, s, 2);
            s += __shfl_xor_sync(0xffffffffu, s, 4);
            rsum[i] = rsum[i] * scale + s;
#pragma unroll
            for (int c = 0; c < 8; c++) O[i][c] *= scale;
        }

        // P -> smem
#pragma unroll
        for (int i = 0; i < 8; i++)
#pragma unroll
            for (int jj = 0; jj < 8; jj++)
                Ps[(ty * 8 + i) * 65 + tx * 8 + jj] = S[i][jj];
        __syncthreads();

        // O += P @ V
#pragma unroll 2
        for (int n = 0; n < 64; n++) {
            float pv[8], vv[8];
#pragma unroll
            for (int i = 0; i < 8; i++) pv[i] = Ps[(ty * 8 + i) * 65 + n];
#pragma unroll
            for (int c = 0; c < 8; c++) vv[c] = Vs[n * 64 + tx * 8 + c];
#pragma unroll
            for (int i = 0; i < 8; i++)
#pragma unroll
                for (int c = 0; c < 8; c++)
                    O[i][c] += pv[i] * vv[c];
        }
    }

    // Normalize and write to g_A
#pragma unroll
    for (int i = 0; i < 8; i++) {
        float inv = 1.0f / rsum[i];
        int row = qt * 128 + ty * 8 + i;
        float4 o0, o1;
        o0.x = O[i][0] * inv; o0.y = O[i][1] * inv;
        o0.z = O[i][2] * inv; o0.w = O[i][3] * inv;
        o1.x = O[i][4] * inv; o1.y = O[i][5] * inv;
        o1.z = O[i][6] * inv; o1.w = O[i][7] * inv;
        *(float4*)(g_A + base + (size_t)row * DM + tx * 8)     = o0;
        *(float4*)(g_A + base + (size_t)row * DM + tx * 8 + 4) = o1;
    }
}

// ---------------------------------------------------------------------------
extern "C" void kernel_launch(void* const* d_in, const int* in_sizes, int n_in,
                              void* d_out, int out_size)
{
    const float* x = 0;
    const float* Ws[4] = {0, 0, 0, 0};
    const float* bs[4] = {0, 0, 0, 0};
    int nw = 0, nb = 0;
    for (int i = 0; i < n_in; i++) {
        if (in_sizes[i] == M_TOT * DM)      x = (const float*)d_in[i];
        else if (in_sizes[i] == DM * DM)    { if (nw < 4) Ws[nw++] = (const float*)d_in[i]; }
        else if (in_sizes[i] == DM)         { if (nb < 4) bs[nb++] = (const float*)d_in[i]; }
    }
    const float *Wq = Ws[0], *Wk = Ws[1], *Wv = Ws[2], *Wo = Ws[3];
    const float *bq = bs[0], *bk = bs[1], *bv = bs[2], *bo = bs[3];
    float* out = (float*)d_out;

    void *pQ, *pK, *pV, *pA;
    cudaGetSymbolAddress(&pQ, g_Q);
    cudaGetSymbolAddress(&pK, g_K);
    cudaGetSymbolAddress(&pV, g_V);
    cudaGetSymbolAddress(&pA, g_A);

    const int gemm_smem = 2 * STAGE_FLOATS * (int)sizeof(float);   // 55296 B
    cudaFuncSetAttribute(gemm_tf32_kernel, cudaFuncAttributeMaxDynamicSharedMemorySize, gemm_smem);

    // 1) Fused Q/K/V projections (tensor cores, 3xTF32, cp.async pipeline)
    gemm_tf32_kernel<<<dim3(M_TOT / GBM, DM / GBN, 3), 256, gemm_smem>>>(
        x, Wq, Wk, Wv, bq, bk, bv, (float*)pQ, (float*)pK, (float*)pV);

    // 2) Causal flash attention v2 (fp32 SIMT, 128-row Q tiles)
    const int attn_smem = (64 * 130 + 64 * 65 + 64 * 64 + 128 * 65) * (int)sizeof(float); // 99584 B
    cudaFuncSetAttribute(attn_kernel, cudaFuncAttributeMaxDynamicSharedMemorySize, attn_smem);
    attn_kernel<<<dim3(SEQ / 128, 4 * N_HEADS), 128, attn_smem>>>();

    // 3) Output projection -> d_out (tensor cores, 3xTF32)
    gemm_tf32_kernel<<<dim3(M_TOT / GBM, DM / GBN, 1), 256, gemm_smem>>>(
        (const float*)pA, Wo, Wo, Wo, bo, bo, bo, out, out, out);
}